// round 5
// baseline (speedup 1.0000x reference)
#include <cuda_runtime.h>

// out[i] = sum_j S[i][j] * w[j]   (S: [n,n] row-major fp32, w: [n] fp32)
// Two rows per CTA: each w load is shared by two S streams (LDG count per
// useful line 2.0 -> 1.5; halves L2 w traffic). 256 threads, float4 loads.
__global__ void __launch_bounds__(256) rowdot2_kernel(
    const float* __restrict__ S,
    const float* __restrict__ w,
    float* __restrict__ out,
    int n)
{
    const int row0 = blockIdx.x * 2;
    const float4* __restrict__ s4a = reinterpret_cast<const float4*>(S + (size_t)row0 * n);
    const float4* __restrict__ s4b = reinterpret_cast<const float4*>(S + (size_t)(row0 + 1) * n);
    const float4* __restrict__ w4  = reinterpret_cast<const float4*>(w);

    const int n4 = n >> 2;        // 4096 float4 per row
    const int bd = blockDim.x;    // 256 -> 16 iterations per thread

    float accA = 0.0f, accB = 0.0f;

    for (int i = threadIdx.x; i < n4; i += bd) {
        float4 wa = w4[i];
        float4 sa = s4a[i];
        float4 sb = s4b[i];
        accA = fmaf(sa.x, wa.x, accA);
        accA = fmaf(sa.y, wa.y, accA);
        accA = fmaf(sa.z, wa.z, accA);
        accA = fmaf(sa.w, wa.w, accA);
        accB = fmaf(sb.x, wa.x, accB);
        accB = fmaf(sb.y, wa.y, accB);
        accB = fmaf(sb.z, wa.z, accB);
        accB = fmaf(sb.w, wa.w, accB);
    }

    // Warp reduce both accumulators
    #pragma unroll
    for (int off = 16; off > 0; off >>= 1) {
        accA += __shfl_down_sync(0xFFFFFFFFu, accA, off);
        accB += __shfl_down_sync(0xFFFFFFFFu, accB, off);
    }

    // Block reduce across 8 warps, both rows
    __shared__ float warp_sums[2][8];
    const int lane = threadIdx.x & 31;
    const int wid  = threadIdx.x >> 5;
    if (lane == 0) {
        warp_sums[0][wid] = accA;
        warp_sums[1][wid] = accB;
    }
    __syncthreads();

    if (wid == 0) {
        float v = (lane < 8) ? warp_sums[0][lane] : 0.0f;
        #pragma unroll
        for (int off = 4; off > 0; off >>= 1)
            v += __shfl_down_sync(0xFFFFFFFFu, v, off);
        if (lane == 0) out[row0] = v;
    } else if (wid == 1) {
        float v = (lane < 8) ? warp_sums[1][lane] : 0.0f;
        #pragma unroll
        for (int off = 4; off > 0; off >>= 1)
            v += __shfl_down_sync(0xFFFFFFFFu, v, off);
        if (lane == 0) out[row0 + 1] = v;
    }
}

extern "C" void kernel_launch(void* const* d_in, const int* in_sizes, int n_in,
                              void* d_out, int out_size) {
    const float* S = (const float*)d_in[0];
    const float* w = (const float*)d_in[1];
    float* out = (float*)d_out;

    const int n = in_sizes[1];  // N = 16384

    rowdot2_kernel<<<n / 2, 256>>>(S, w, out, n);
}

// round 6
// speedup vs baseline: 1.0267x; 1.0267x over previous
#include <cuda_runtime.h>

// out[i] = sum_j S[i][j] * w[j]   (S: [n,n] row-major fp32, w: [n] fp32)
// Two rows per CTA (each w load feeds two S streams -> 25% fewer LDGs)
// with a hard 8-CTAs/SM floor so ptxas fits 32 regs and occupancy stays ~96%.
__global__ void __launch_bounds__(256, 8) rowdot2_hiocc_kernel(
    const float* __restrict__ S,
    const float* __restrict__ w,
    float* __restrict__ out,
    int n)
{
    const int row0 = blockIdx.x * 2;
    const float4* __restrict__ s4a = reinterpret_cast<const float4*>(S + (size_t)row0 * n);
    const float4* __restrict__ s4b = reinterpret_cast<const float4*>(S + (size_t)(row0 + 1) * n);
    const float4* __restrict__ w4  = reinterpret_cast<const float4*>(w);

    const int n4 = n >> 2;  // 4096 float4 per row

    float accA = 0.0f, accB = 0.0f;

    // 16 iterations/thread at n=16384. Keep the body minimal so it fits
    // the 32-register budget without spills.
    for (int i = threadIdx.x; i < n4; i += 256) {
        float4 wa = w4[i];
        float4 sa = s4a[i];
        float4 sb = s4b[i];
        accA = fmaf(sa.x, wa.x, accA);
        accA = fmaf(sa.y, wa.y, accA);
        accA = fmaf(sa.z, wa.z, accA);
        accA = fmaf(sa.w, wa.w, accA);
        accB = fmaf(sb.x, wa.x, accB);
        accB = fmaf(sb.y, wa.y, accB);
        accB = fmaf(sb.z, wa.z, accB);
        accB = fmaf(sb.w, wa.w, accB);
    }

    // Warp reduce both accumulators
    #pragma unroll
    for (int off = 16; off > 0; off >>= 1) {
        accA += __shfl_down_sync(0xFFFFFFFFu, accA, off);
        accB += __shfl_down_sync(0xFFFFFFFFu, accB, off);
    }

    __shared__ float warp_sums[2][8];
    const int lane = threadIdx.x & 31;
    const int wid  = threadIdx.x >> 5;
    if (lane == 0) {
        warp_sums[0][wid] = accA;
        warp_sums[1][wid] = accB;
    }
    __syncthreads();

    if (wid == 0) {
        float v = (lane < 8) ? warp_sums[0][lane] : 0.0f;
        #pragma unroll
        for (int off = 4; off > 0; off >>= 1)
            v += __shfl_down_sync(0xFFFFFFFFu, v, off);
        if (lane == 0) out[row0] = v;
    } else if (wid == 1) {
        float v = (lane < 8) ? warp_sums[1][lane] : 0.0f;
        #pragma unroll
        for (int off = 4; off > 0; off >>= 1)
            v += __shfl_down_sync(0xFFFFFFFFu, v, off);
        if (lane == 0) out[row0 + 1] = v;
    }
}

extern "C" void kernel_launch(void* const* d_in, const int* in_sizes, int n_in,
                              void* d_out, int out_size) {
    const float* S = (const float*)d_in[0];
    const float* w = (const float*)d_in[1];
    float* out = (float*)d_out;

    const int n = in_sizes[1];  // N = 16384

    rowdot2_hiocc_kernel<<<n / 2, 256>>>(S, w, out, n);
}